// round 2
// baseline (speedup 1.0000x reference)
#include <cuda_runtime.h>

#define N 8192
#define D 256
#define TILE 128
#define KC 16
#define NSPLIT 4
#define NT (N / TILE)                 // 64 column tiles
#define CT_PER_SPLIT (NT / NSPLIT)    // 16 per split

__device__ float g_norms[N];
__device__ float g_maxpos[NSPLIT * N];
__device__ float g_minneg[NSPLIT * N];

// ---------------------------------------------------------------------------
// Kernel 1: per-row squared norms
// ---------------------------------------------------------------------------
__global__ void norms_kernel(const float* __restrict__ feat) {
    int row = blockIdx.x * blockDim.x + threadIdx.x;
    if (row >= N) return;
    const float4* f = reinterpret_cast<const float4*>(feat + (size_t)row * D);
    float s = 0.f;
#pragma unroll
    for (int i = 0; i < D / 4; i++) {
        float4 v = f[i];
        s += v.x * v.x + v.y * v.y + v.z * v.z + v.w * v.w;
    }
    g_norms[row] = s;
}

// ---------------------------------------------------------------------------
// Kernel 2: fused Gram-tile + hard mining.
// Block: 256 threads, computes a 128x128 tile of dot products at a time.
// grid.x = row tile (64), grid.y = column split (4) -> 256 blocks.
// Thread (tx,ty) owns rows {ty*4+i, 64+ty*4+i} and cols {tx*4+j, 64+tx*4+j}.
// ---------------------------------------------------------------------------
__global__ __launch_bounds__(256, 2)
void triplet_tile_kernel(const float* __restrict__ feat,
                         const int* __restrict__ labels) {
    __shared__ float As[KC][TILE];
    __shared__ float Bs[KC][TILE];
    __shared__ int   sColLab[TILE];
    __shared__ float sColNorm[TILE];
    __shared__ int   sRowLab[TILE];
    __shared__ float sRowNorm[TILE];

    const int tid = threadIdx.x;
    const int tx = tid & 15;
    const int ty = tid >> 4;
    const int rowBase = blockIdx.x * TILE;
    const int split = blockIdx.y;

    if (tid < TILE) {
        sRowLab[tid]  = labels[rowBase + tid];
        sRowNorm[tid] = g_norms[rowBase + tid];
    }

    float maxpos[8], minneg[8];
#pragma unroll
    for (int i = 0; i < 8; i++) { maxpos[i] = -1e30f; minneg[i] = 1e30f; }

    for (int ct = split * CT_PER_SPLIT; ct < (split + 1) * CT_PER_SPLIT; ct++) {
        const int colBase = ct * TILE;
        __syncthreads();  // protect sColLab/sColNorm from previous iteration's readers
        if (tid < TILE) {
            sColLab[tid]  = labels[colBase + tid];
            sColNorm[tid] = g_norms[colBase + tid];
        }

        float acc[8][8];
#pragma unroll
        for (int i = 0; i < 8; i++)
#pragma unroll
            for (int j = 0; j < 8; j++) acc[i][j] = 0.f;

        for (int k0 = 0; k0 < D; k0 += KC) {
            __syncthreads();
            {
                int r  = tid >> 2;           // 0..63
                int kk = (tid & 3) * 4;      // 0,4,8,12
#pragma unroll
                for (int it = 0; it < 2; it++) {
                    int rr = r + it * 64;
                    float4 va = *reinterpret_cast<const float4*>(
                        feat + (size_t)(rowBase + rr) * D + k0 + kk);
                    As[kk + 0][rr] = va.x; As[kk + 1][rr] = va.y;
                    As[kk + 2][rr] = va.z; As[kk + 3][rr] = va.w;
                    float4 vb = *reinterpret_cast<const float4*>(
                        feat + (size_t)(colBase + rr) * D + k0 + kk);
                    Bs[kk + 0][rr] = vb.x; Bs[kk + 1][rr] = vb.y;
                    Bs[kk + 2][rr] = vb.z; Bs[kk + 3][rr] = vb.w;
                }
            }
            __syncthreads();
#pragma unroll
            for (int k = 0; k < KC; k++) {
                float4 a0 = *reinterpret_cast<const float4*>(&As[k][ty * 4]);
                float4 a1 = *reinterpret_cast<const float4*>(&As[k][64 + ty * 4]);
                float4 b0 = *reinterpret_cast<const float4*>(&Bs[k][tx * 4]);
                float4 b1 = *reinterpret_cast<const float4*>(&Bs[k][64 + tx * 4]);
                float a[8] = {a0.x, a0.y, a0.z, a0.w, a1.x, a1.y, a1.z, a1.w};
                float b[8] = {b0.x, b0.y, b0.z, b0.w, b1.x, b1.y, b1.z, b1.w};
#pragma unroll
                for (int i = 0; i < 8; i++)
#pragma unroll
                    for (int j = 0; j < 8; j++)
                        acc[i][j] = fmaf(a[i], b[j], acc[i][j]);
            }
        }

        // Epilogue: distance + hard-mining update for this 128-wide column tile.
        int   clab[8]; float cn[8];
        int   rlab[8]; float rn[8];
#pragma unroll
        for (int j = 0; j < 8; j++) {
            int cc = (j < 4) ? tx * 4 + j : 64 + tx * 4 + (j - 4);
            clab[j] = sColLab[cc]; cn[j] = sColNorm[cc];
        }
#pragma unroll
        for (int i = 0; i < 8; i++) {
            int rr = (i < 4) ? ty * 4 + i : 64 + ty * 4 + (i - 4);
            rlab[i] = sRowLab[rr]; rn[i] = sRowNorm[rr];
        }
#pragma unroll
        for (int i = 0; i < 8; i++) {
            int rr = (i < 4) ? ty * 4 + i : 64 + ty * 4 + (i - 4);
            int grow = rowBase + rr;
#pragma unroll
            for (int j = 0; j < 8; j++) {
                int cc = (j < 4) ? tx * 4 + j : 64 + tx * 4 + (j - 4);
                int gcol = colBase + cc;
                float sq = rn[i] + cn[j] - 2.f * acc[i][j];
                sq = fmaxf(sq, 0.f);
                float dist = sqrtf(sq);
                bool same = (rlab[i] == clab[j]);
                if (same) {
                    if (grow != gcol) maxpos[i] = fmaxf(maxpos[i], dist);
                } else {
                    minneg[i] = fminf(minneg[i], dist);
                }
            }
        }
    }

    // Reduce across the 16 threads (tx) that share each row; lanes 0..15 and
    // 16..31 are distinct ty groups, masks <16 stay within each 16-lane half.
#pragma unroll
    for (int i = 0; i < 8; i++) {
#pragma unroll
        for (int m = 1; m < 16; m <<= 1) {
            maxpos[i] = fmaxf(maxpos[i], __shfl_xor_sync(0xffffffffu, maxpos[i], m));
            minneg[i] = fminf(minneg[i], __shfl_xor_sync(0xffffffffu, minneg[i], m));
        }
    }
    if (tx == 0) {
#pragma unroll
        for (int i = 0; i < 8; i++) {
            int rr = (i < 4) ? ty * 4 + i : 64 + ty * 4 + (i - 4);
            g_maxpos[split * N + rowBase + rr] = maxpos[i];
            g_minneg[split * N + rowBase + rr] = minneg[i];
        }
    }
}

// ---------------------------------------------------------------------------
// Kernel 3: merge splits, apply fallbacks, margin-ranking mean.
// ---------------------------------------------------------------------------
__global__ void finalize_kernel(float* __restrict__ out) {
    __shared__ float ssum[256];
    int t = threadIdx.x;
    float s = 0.f;
    for (int r = t; r < N; r += 256) {
        float mp = -1e30f, mn = 1e30f;
#pragma unroll
        for (int sp = 0; sp < NSPLIT; sp++) {
            mp = fmaxf(mp, g_maxpos[sp * N + r]);
            mn = fminf(mn, g_minneg[sp * N + r]);
        }
        float ap = (mp > -1e29f) ? mp : 0.f;       // no positives -> 0
        float an = (mn <  1e29f) ? mn : 1e6f;      // no negatives -> NEG_FALLBACK
        s += fmaxf(0.f, 0.3f + ap - an);
    }
    ssum[t] = s;
    __syncthreads();
    for (int off = 128; off > 0; off >>= 1) {
        if (t < off) ssum[t] += ssum[t + off];
        __syncthreads();
    }
    if (t == 0) out[0] = ssum[0] / (float)N;
}

// ---------------------------------------------------------------------------
extern "C" void kernel_launch(void* const* d_in, const int* in_sizes, int n_in,
                              void* d_out, int out_size) {
    const float* feat = (const float*)d_in[0];
    const int* labels = (const int*)d_in[1];
    float* out = (float*)d_out;

    norms_kernel<<<(N + 255) / 256, 256>>>(feat);
    dim3 grid(N / TILE, NSPLIT);
    triplet_tile_kernel<<<grid, 256>>>(feat, labels);
    finalize_kernel<<<1, 256>>>(out);
}

// round 4
// speedup vs baseline: 2.8048x; 2.8048x over previous
#include <cuda_runtime.h>
#include <cuda_bf16.h>
#include <cstdint>

#define N 8192
#define D 256
#define KE 768              // packed K: [hi|hi|lo] . [hi|lo|hi]
#define BM 128
#define BN 128
#define BK 32
#define THREADS 256
#define ITERS (KE / BK)     // 24

// ---------------------------------------------------------------------------
// Device scratch (no cudaMalloc allowed)
// ---------------------------------------------------------------------------
__device__ __nv_bfloat16 g_pa[N * KE];   // [hi | hi | lo]
__device__ __nv_bfloat16 g_pb[N * KE];   // [hi | lo | hi]
__device__ float g_norms[N];
__device__ int   g_maxpos_i[N];          // encoded floats, INT_MIN = none
__device__ int   g_minneg_i[N];          // encoded floats, INT_MAX = none
__device__ float g_partial[32];

// order-preserving float<->int encoding (works for negatives)
__device__ __forceinline__ int f2i(float f) {
    int i = __float_as_int(f);
    return i >= 0 ? i : (i ^ 0x7fffffff);
}
__device__ __forceinline__ float i2f(int i) {
    return __int_as_float(i >= 0 ? i : (i ^ 0x7fffffff));
}
__device__ __forceinline__ uint32_t smem_u32(const void* p) {
    uint32_t a;
    asm("{ .reg .u64 t; cvta.to.shared.u64 t, %1; cvt.u32.u64 %0, t; }"
        : "=r"(a) : "l"(p));
    return a;
}
__device__ __forceinline__ void cp16(uint32_t s, const void* g) {
    asm volatile("cp.async.cg.shared.global [%0], [%1], 16;\n"
                 :: "r"(s), "l"(g) : "memory");
}
#define CP_COMMIT() asm volatile("cp.async.commit_group;" ::: "memory")
#define CP_WAIT(n)  asm volatile("cp.async.wait_group %0;" :: "n"(n) : "memory")

#define LDSM_X4(r0, r1, r2, r3, a)                                            \
    asm volatile("ldmatrix.sync.aligned.m8n8.x4.shared.b16 {%0,%1,%2,%3}, [%4];" \
                 : "=r"(r0), "=r"(r1), "=r"(r2), "=r"(r3) : "r"(a))

#define MMA_BF16(c, a0, a1, a2, a3, b0, b1)                                   \
    asm volatile(                                                             \
        "mma.sync.aligned.m16n8k16.row.col.f32.bf16.bf16.f32 "                \
        "{%0,%1,%2,%3}, {%4,%5,%6,%7}, {%8,%9}, {%0,%1,%2,%3};"               \
        : "+f"((c)[0]), "+f"((c)[1]), "+f"((c)[2]), "+f"((c)[3])              \
        : "r"(a0), "r"(a1), "r"(a2), "r"(a3), "r"(b0), "r"(b1))

// ---------------------------------------------------------------------------
// Prep 1: fp32 -> packed split-bf16 operands
// ---------------------------------------------------------------------------
__global__ void convert_kernel(const float* __restrict__ feat) {
    int i = blockIdx.x * blockDim.x + threadIdx.x;   // over N*D
    if (i >= N * D) return;
    int r = i / D, c = i % D;
    float x = feat[i];
    __nv_bfloat16 h = __float2bfloat16(x);
    __nv_bfloat16 l = __float2bfloat16(x - __bfloat162float(h));
    size_t base = (size_t)r * KE + c;
    g_pa[base]           = h;
    g_pa[base + D]       = h;
    g_pa[base + 2 * D]   = l;
    g_pb[base]           = h;
    g_pb[base + D]       = l;
    g_pb[base + 2 * D]   = h;
}

// ---------------------------------------------------------------------------
// Prep 2: exact fp32 row norms + mining accumulator init
// ---------------------------------------------------------------------------
__global__ void norms_init_kernel(const float* __restrict__ feat) {
    int gtid = blockIdx.x * blockDim.x + threadIdx.x;
    int row = gtid >> 5;
    int lane = gtid & 31;
    if (row >= N) return;
    const float4* f = reinterpret_cast<const float4*>(feat + (size_t)row * D);
    float s = 0.f;
#pragma unroll
    for (int i = 0; i < 2; i++) {
        float4 v = f[lane + 32 * i];
        s += v.x * v.x + v.y * v.y + v.z * v.z + v.w * v.w;
    }
#pragma unroll
    for (int m = 16; m > 0; m >>= 1) s += __shfl_xor_sync(0xffffffffu, s, m);
    if (lane == 0) {
        g_norms[row] = s;
        g_maxpos_i[row] = INT_MIN;
        g_minneg_i[row] = INT_MAX;
    }
}

// ---------------------------------------------------------------------------
// Main: HMMA Gram tile (128x128) + fused hard mining on v = cn - 2*dot
// ---------------------------------------------------------------------------
#define LDA 40   // smem row stride in bf16 elems (conflict-free for ldmatrix)

__global__ __launch_bounds__(THREADS, 2)
void gram_kernel(const int* __restrict__ labels) {
    __shared__ __nv_bfloat16 As[2][BM * LDA];
    __shared__ __nv_bfloat16 Bs[2][BN * LDA];
    __shared__ int   sColLab[BN];
    __shared__ float sColNorm[BN];
    __shared__ int   sRowLab[BM];
    __shared__ int   sMp[BM];
    __shared__ int   sMn[BM];

    const int tid = threadIdx.x;
    const int lane = tid & 31;
    const int wid = tid >> 5;
    const int warp_m = wid >> 2;          // 0..1  (64 rows each)
    const int warp_n = wid & 3;           // 0..3  (32 cols each)
    const int rowBase = blockIdx.x * BM;
    const int colBase = blockIdx.y * BN;

    if (tid < BM) {
        sColLab[tid]  = labels[colBase + tid];
        sColNorm[tid] = g_norms[colBase + tid];
        sRowLab[tid]  = labels[rowBase + tid];
        sMp[tid] = INT_MIN;
        sMn[tid] = INT_MAX;
    }

    const uint32_t sA[2] = {smem_u32(&As[0][0]), smem_u32(&As[1][0])};
    const uint32_t sB[2] = {smem_u32(&Bs[0][0]), smem_u32(&Bs[1][0])};

    // per-lane ldmatrix byte offsets
    const uint32_t aOff = ((warp_m * 64 + (lane & 15)) * LDA + (lane >> 4) * 8) * 2;
    const uint32_t bOff = ((warp_n * 32 + (lane & 7) + ((lane >> 4) & 1) * 8) * LDA
                          + ((lane >> 3) & 1) * 8) * 2;

    const __nv_bfloat16* ga = g_pa + (size_t)rowBase * KE;
    const __nv_bfloat16* gb = g_pb + (size_t)colBase * KE;

    auto load_stage = [&](int kt, int buf) {
        const int k0 = kt * BK;
#pragma unroll
        for (int i = 0; i < 2; i++) {               // A: 512 chunks of 16B
            int idx = tid + i * THREADS;
            int r = idx >> 2, c = idx & 3;
            cp16(sA[buf] + (r * LDA + c * 8) * 2, ga + (size_t)r * KE + k0 + c * 8);
        }
#pragma unroll
        for (int i = 0; i < 2; i++) {               // B: 512 chunks
            int idx = tid + i * THREADS;
            int r = idx >> 2, c = idx & 3;
            cp16(sB[buf] + (r * LDA + c * 8) * 2, gb + (size_t)r * KE + k0 + c * 8);
        }
        CP_COMMIT();
    };

    float acc[4][4][4];
#pragma unroll
    for (int i = 0; i < 4; i++)
#pragma unroll
        for (int j = 0; j < 4; j++)
#pragma unroll
            for (int e = 0; e < 4; e++) acc[i][j][e] = 0.f;

    load_stage(0, 0);

    for (int it = 0; it < ITERS; ++it) {
        const int buf = it & 1;
        if (it + 1 < ITERS) load_stage(it + 1, buf ^ 1);
        if (it + 1 < ITERS) { CP_WAIT(1); } else { CP_WAIT(0); }
        __syncthreads();

#pragma unroll
        for (int ks = 0; ks < 2; ks++) {            // two k16 steps per BK=32
            uint32_t aF[4][4], bF[2][4];
#pragma unroll
            for (int mt = 0; mt < 4; mt++)
                LDSM_X4(aF[mt][0], aF[mt][1], aF[mt][2], aF[mt][3],
                        sA[buf] + aOff + mt * (16 * LDA * 2) + ks * 32);
#pragma unroll
            for (int ng = 0; ng < 2; ng++)
                LDSM_X4(bF[ng][0], bF[ng][1], bF[ng][2], bF[ng][3],
                        sB[buf] + bOff + ng * (16 * LDA * 2) + ks * 32);
#pragma unroll
            for (int mt = 0; mt < 4; mt++) {
#pragma unroll
                for (int nt = 0; nt < 4; nt++) {
                    const int ng = nt >> 1;
                    const int hi = (nt & 1) << 1;   // 0 or 2
                    MMA_BF16(acc[mt][nt], aF[mt][0], aF[mt][1], aF[mt][2], aF[mt][3],
                             bF[ng][hi], bF[ng][hi + 1]);
                }
            }
        }
        __syncthreads();
    }

    // ---- epilogue: hard mining on v = cn - 2*dot (sqrt deferred) ----
    {
        float cn8[8]; int clab8[8], gcol8[8];
#pragma unroll
        for (int nt = 0; nt < 4; nt++)
#pragma unroll
            for (int e = 0; e < 2; e++) {
                int cc = warp_n * 32 + nt * 8 + (lane & 3) * 2 + e;
                cn8[nt * 2 + e] = sColNorm[cc];
                clab8[nt * 2 + e] = sColLab[cc];
                gcol8[nt * 2 + e] = colBase + cc;
            }
        int rl8[8], grow8[8];
#pragma unroll
        for (int mt = 0; mt < 4; mt++)
#pragma unroll
            for (int h = 0; h < 2; h++) {
                int rr = warp_m * 64 + mt * 16 + (lane >> 2) + h * 8;
                rl8[mt * 2 + h] = sRowLab[rr];
                grow8[mt * 2 + h] = rowBase + rr;
            }

        float mp[8], mn[8];
#pragma unroll
        for (int i = 0; i < 8; i++) { mp[i] = -3.0e38f; mn[i] = 3.0e38f; }

#pragma unroll
        for (int mt = 0; mt < 4; mt++)
#pragma unroll
            for (int h = 0; h < 2; h++) {
                const int ri = mt * 2 + h;
#pragma unroll
                for (int nt = 0; nt < 4; nt++)
#pragma unroll
                    for (int e = 0; e < 2; e++) {
                        const int ci = nt * 2 + e;
                        float v = fmaf(-2.f, acc[mt][nt][h * 2 + e], cn8[ci]);
                        bool same = (rl8[ri] == clab8[ci]);
                        if (same) {
                            if (grow8[ri] != gcol8[ci]) mp[ri] = fmaxf(mp[ri], v);
                        } else {
                            mn[ri] = fminf(mn[ri], v);
                        }
                    }
            }

        // reduce across the 4 lanes sharing each row (same lane>>2 group)
#pragma unroll
        for (int i = 0; i < 8; i++) {
#pragma unroll
            for (int m = 1; m < 4; m <<= 1) {
                mp[i] = fmaxf(mp[i], __shfl_xor_sync(0xffffffffu, mp[i], m));
                mn[i] = fminf(mn[i], __shfl_xor_sync(0xffffffffu, mn[i], m));
            }
        }
        if ((lane & 3) == 0) {
#pragma unroll
            for (int mt = 0; mt < 4; mt++)
#pragma unroll
                for (int h = 0; h < 2; h++) {
                    int rr = warp_m * 64 + mt * 16 + (lane >> 2) + h * 8;
                    float vp = mp[mt * 2 + h], vn = mn[mt * 2 + h];
                    if (vp > -2.9e38f) atomicMax(&sMp[rr], f2i(vp));
                    if (vn <  2.9e38f) atomicMin(&sMn[rr], f2i(vn));
                }
        }
    }
    __syncthreads();
    if (tid < BM) {
        if (sMp[tid] != INT_MIN) atomicMax(&g_maxpos_i[rowBase + tid], sMp[tid]);
        if (sMn[tid] != INT_MAX) atomicMin(&g_minneg_i[rowBase + tid], sMn[tid]);
    }
}

// ---------------------------------------------------------------------------
// Finalize: per-row sqrt + margin, deterministic two-phase mean
// ---------------------------------------------------------------------------
__global__ void finalize1_kernel() {
    __shared__ float ssum[256];
    int t = threadIdx.x;
    int r = blockIdx.x * 256 + t;
    float rn = g_norms[r];
    int ep = g_maxpos_i[r];
    int en = g_minneg_i[r];
    float ap = (ep == INT_MIN) ? 0.f : sqrtf(fmaxf(rn + i2f(ep), 0.f));
    float an = (en == INT_MAX) ? 1e6f : sqrtf(fmaxf(rn + i2f(en), 0.f));
    ssum[t] = fmaxf(0.f, 0.3f + ap - an);
    __syncthreads();
    for (int off = 128; off > 0; off >>= 1) {
        if (t < off) ssum[t] += ssum[t + off];
        __syncthreads();
    }
    if (t == 0) g_partial[blockIdx.x] = ssum[0];
}
__global__ void finalize2_kernel(float* __restrict__ out) {
    float v = g_partial[threadIdx.x];
#pragma unroll
    for (int m = 16; m > 0; m >>= 1) v += __shfl_xor_sync(0xffffffffu, v, m);
    if (threadIdx.x == 0) out[0] = v / (float)N;
}

// ---------------------------------------------------------------------------
extern "C" void kernel_launch(void* const* d_in, const int* in_sizes, int n_in,
                              void* d_out, int out_size) {
    const float* feat = (const float*)d_in[0];
    const int* labels = (const int*)d_in[1];
    float* out = (float*)d_out;

    convert_kernel<<<(N * D + 255) / 256, 256>>>(feat);
    norms_init_kernel<<<(N * 32 + 255) / 256, 256>>>(feat);
    gram_kernel<<<dim3(N / BM, N / BN), THREADS>>>(labels);
    finalize1_kernel<<<N / 256, 256>>>();
    finalize2_kernel<<<1, 32>>>(out);
}